// round 1
// baseline (speedup 1.0000x reference)
#include <cuda_runtime.h>
#include <math.h>
#include <stdint.h>

// Problem sizes (fixed for this problem)
#define B_SZ 4096
#define I_SZ 1024
#define H_SZ 2048
#define O_SZ 256
#define M_SZ 100
#define KCOMB (I_SZ + 3*H_SZ)   // 7168

// GEMM tiling
#define BM 128
#define BN 128
#define BK 16
#define SKEW 4
#define BKP (BK + SKEW)          // 20 floats per smem row
#define THREADS 256

enum { M_FUSED = 0, M_LCPRE = 1, M_OUT = 2, M_HPROJ = 3, M_CELL = 4 };

// Scratch (static __device__ arrays: allocation-free per harness rules)
__device__ float g_mid[(size_t)B_SZ * M_SZ];        // relu(combined@W_cm2^T + b)
__device__ float g_lc [(size_t)B_SZ * H_SZ];        // lc accumulator

struct GP {
    const float* seg[4];     // A operand segments (row-major [B, segLd])
    int   segEnd[4];         // cumulative K ends
    int   segLd[4];
    int   nSeg;
    int   K;
    int   N;                 // logical N covered by grid (also Wrows for non-fused)
    const float* W;          // [rows, K] row-major
    const float* Wb;         // fused: second weight (W_cm2)
    const float* bias;       // primary bias [per col]
    const float* bias_b;     // fused: second bias
    const float* bias2;      // extra additive vec (lcpre: self.bias)
    float* C;                // primary output
};

__device__ __forceinline__ uint32_t f2tf(float x) {
    uint32_t r;
    asm("cvt.rna.tf32.f32 %0, %1;" : "=r"(r) : "f"(x));
    return r;
}
__device__ __forceinline__ uint32_t smem_u32(const void* p) {
    return (uint32_t)__cvta_generic_to_shared(p);
}
__device__ __forceinline__ void cp16(uint32_t s, const void* g, int bytes) {
    asm volatile("cp.async.cg.shared.global [%0], [%1], 16, %2;\n"
                 :: "r"(s), "l"(g), "r"(bytes));
}
__device__ __forceinline__ void cp_commit() {
    asm volatile("cp.async.commit_group;\n");
}

template <int MODE>
__device__ __forceinline__ void epi_store(const GP& p, int row, int col, float v) {
    if (MODE == M_FUSED) {
        if (col < H_SZ) {
            p.C[(size_t)row * H_SZ + col] = v + p.bias[col];
        } else {
            int c2 = col - H_SZ;
            if (c2 < M_SZ) {
                float x = v + p.bias_b[c2];
                g_mid[(size_t)row * M_SZ + c2] = fmaxf(x, 0.0f);
            }
        }
    } else if (MODE == M_LCPRE) {
        g_lc[(size_t)row * H_SZ + col] = v + p.bias[col] + p.bias2[col];
    } else if (MODE == M_OUT) {
        p.C[(size_t)row * O_SZ + col] = v + p.bias[col];
    } else if (MODE == M_HPROJ) {
        float hp = v + p.bias[col];
        p.C[(size_t)row * H_SZ + col] = hp;                 // new_prev_hidden
        size_t idx = (size_t)row * H_SZ + col;
        g_lc[idx] = g_lc[idx] + hp;                         // lc = lc_pre + h_proj
    } else if (MODE == M_CELL) {
        p.C[(size_t)row * H_SZ + col] = tanhf(v + p.bias[col]);
    }
}

template <int MODE>
__global__ void __launch_bounds__(THREADS)
gemm_tf32(GP p)
{
    __shared__ __align__(16) float As[2][BM][BKP];
    __shared__ __align__(16) float Bs[2][BN][BKP];

    const int mBase = blockIdx.y * BM;
    const int nBase = blockIdx.x * BN;
    const int tid  = threadIdx.x;
    const int lane = tid & 31;
    const int wid  = tid >> 5;
    const int wMB  = (wid & 3) * 32;   // warp M offset (4 warps in M)
    const int wNB  = (wid >> 2) * 64;  // warp N offset (2 warps in N)
    const int g    = lane >> 2;        // group id 0..7
    const int l    = lane & 3;         // lane-in-group 0..3

    // B-side selection (uniform per CTA)
    const float* Wp = p.W;
    int nOff  = 0;
    int Wrows = p.N;
    if (MODE == M_FUSED) {
        if (nBase >= H_SZ) { Wp = p.Wb; nOff = H_SZ; Wrows = M_SZ; }
        else               { Wrows = H_SZ; }
    }

    // A-side base (scratch-backed modes read __device__ arrays directly)
    const float* Abase;
    int Ald;
    if (MODE == M_OUT)       { Abase = g_mid; Ald = M_SZ; }
    else if (MODE == M_CELL) { Abase = g_lc;  Ald = H_SZ; }
    else                     { Abase = p.seg[0]; Ald = p.segLd[0]; }

    const int K  = p.K;
    const int nK = (K + BK - 1) / BK;

    float acc[2][8][4];
#pragma unroll
    for (int a = 0; a < 2; a++)
#pragma unroll
        for (int b = 0; b < 8; b++)
#pragma unroll
            for (int c = 0; c < 4; c++) acc[a][b][c] = 0.0f;

    auto loadAB = [&](int buf, int kt) {
        const int k0 = kt * BK;
        // ---- A tile: BM x BK, 512 float4s, 2 per thread ----
#pragma unroll
        for (int it = 0; it < 2; it++) {
            int i   = tid + it * THREADS;
            int row = i >> 2;
            int col = (i & 3) << 2;
            int kg  = k0 + col;
            const float* src;
            int bytes;
            if (MODE == M_FUSED) {
                // segment boundaries are all multiples of BK; a float4 never straddles
                int s = 0, start = 0;
                if (kg >= p.segEnd[0]) { s = 1; start = p.segEnd[0]; }
                if (kg >= p.segEnd[1]) { s = 2; start = p.segEnd[1]; }
                if (kg >= p.segEnd[2]) { s = 3; start = p.segEnd[2]; }
                src = p.seg[s] + (size_t)(mBase + row) * p.segLd[s] + (kg - start);
                bytes = 16;
            } else {
                int rem = K - kg;
                bytes = (rem >= 4) ? 16 : ((rem > 0) ? rem * 4 : 0);
                src = (rem > 0) ? (Abase + (size_t)(mBase + row) * Ald + kg) : Abase;
            }
            cp16(smem_u32(&As[buf][row][col]), src, bytes);
        }
        // ---- B tile: BN x BK (W rows are K-contiguous) ----
#pragma unroll
        for (int it = 0; it < 2; it++) {
            int i   = tid + it * THREADS;
            int row = i >> 2;
            int col = (i & 3) << 2;
            int kg  = k0 + col;
            int wr  = nBase + row - nOff;
            int rem = K - kg;
            int bytes = (rem >= 4) ? 16 : ((rem > 0) ? rem * 4 : 0);
            bool valid = (wr < Wrows) && (rem > 0);
            if (wr >= Wrows) bytes = 0;
            const float* src = valid ? (Wp + (size_t)wr * K + kg) : Wp;
            cp16(smem_u32(&Bs[buf][row][col]), src, bytes);
        }
        cp_commit();
    };

    // prologue: fill both buffers
    loadAB(0, 0);
    if (nK > 1) loadAB(1, 1);

    for (int kt = 0; kt < nK; kt++) {
        if (kt < nK - 1) asm volatile("cp.async.wait_group 1;\n");
        else             asm volatile("cp.async.wait_group 0;\n");
        __syncthreads();
        const int buf = kt & 1;

#pragma unroll
        for (int kk = 0; kk < BK; kk += 8) {
            uint32_t af[2][4];
#pragma unroll
            for (int mi = 0; mi < 2; mi++) {
                int r0 = wMB + mi * 16 + g;
                af[mi][0] = f2tf(As[buf][r0    ][kk + l    ]);
                af[mi][1] = f2tf(As[buf][r0 + 8][kk + l    ]);
                af[mi][2] = f2tf(As[buf][r0    ][kk + l + 4]);
                af[mi][3] = f2tf(As[buf][r0 + 8][kk + l + 4]);
            }
            uint32_t bf[8][2];
#pragma unroll
            for (int ni = 0; ni < 8; ni++) {
                int rn = wNB + ni * 8 + g;
                bf[ni][0] = f2tf(Bs[buf][rn][kk + l    ]);
                bf[ni][1] = f2tf(Bs[buf][rn][kk + l + 4]);
            }
#pragma unroll
            for (int mi = 0; mi < 2; mi++)
#pragma unroll
                for (int ni = 0; ni < 8; ni++) {
                    asm volatile(
                        "mma.sync.aligned.m16n8k8.row.col.f32.tf32.tf32.f32 "
                        "{%0,%1,%2,%3}, {%4,%5,%6,%7}, {%8,%9}, {%0,%1,%2,%3};\n"
                        : "+f"(acc[mi][ni][0]), "+f"(acc[mi][ni][1]),
                          "+f"(acc[mi][ni][2]), "+f"(acc[mi][ni][3])
                        : "r"(af[mi][0]), "r"(af[mi][1]),
                          "r"(af[mi][2]), "r"(af[mi][3]),
                          "r"(bf[ni][0]), "r"(bf[ni][1]));
                }
        }
        __syncthreads();
        if (kt + 2 < nK) loadAB(buf, kt + 2);
    }

    // epilogue: mma C layout -> c0:(g, 2l) c1:(g, 2l+1) c2:(g+8, 2l) c3:(g+8, 2l+1)
#pragma unroll
    for (int mi = 0; mi < 2; mi++) {
        int r0 = mBase + wMB + mi * 16 + g;
#pragma unroll
        for (int ni = 0; ni < 8; ni++) {
            int c0 = nBase + wNB + ni * 8 + l * 2;
            epi_store<MODE>(p, r0,     c0,     acc[mi][ni][0]);
            epi_store<MODE>(p, r0,     c0 + 1, acc[mi][ni][1]);
            epi_store<MODE>(p, r0 + 8, c0,     acc[mi][ni][2]);
            epi_store<MODE>(p, r0 + 8, c0 + 1, acc[mi][ni][3]);
        }
    }
}

extern "C" void kernel_launch(void* const* d_in, const int* in_sizes, int n_in,
                              void* d_out, int out_size)
{
    const float* input = (const float*)d_in[0];
    const float* hidden = (const float*)d_in[1];
    const float* prevh  = (const float*)d_in[2];
    const float* cell   = (const float*)d_in[3];
    const float* W_ch2 = (const float*)d_in[4];
    const float* b_ch2 = (const float*)d_in[5];
    const float* W_cm2 = (const float*)d_in[6];
    const float* b_cm2 = (const float*)d_in[7];
    const float* W_mo  = (const float*)d_in[8];
    const float* b_mo  = (const float*)d_in[9];
    const float* W_ci  = (const float*)d_in[10];
    const float* b_ci  = (const float*)d_in[11];
    const float* W_ch  = (const float*)d_in[12];
    const float* b_ch  = (const float*)d_in[13];
    const float* W_fc  = (const float*)d_in[14];
    const float* b_fc  = (const float*)d_in[15];
    const float* biasv = (const float*)d_in[16];

    float* out        = (float*)d_out;                         // [B, 256]
    float* new_hidden = out + (size_t)B_SZ * O_SZ;             // [B, 2048]
    float* new_cell   = new_hidden + (size_t)B_SZ * H_SZ;      // [B, 2048]
    float* new_prevh  = new_cell + (size_t)B_SZ * H_SZ;        // [B, 2048]

    dim3 block(THREADS);

    // K1: fused G1+G2 — new_hidden (cols 0..2047) + relu-mid (cols 2048..2147)
    {
        GP p = {};
        p.seg[0] = input; p.seg[1] = hidden; p.seg[2] = prevh; p.seg[3] = cell;
        p.segEnd[0] = I_SZ; p.segEnd[1] = I_SZ + H_SZ;
        p.segEnd[2] = I_SZ + 2 * H_SZ; p.segEnd[3] = KCOMB;
        p.segLd[0] = I_SZ; p.segLd[1] = H_SZ; p.segLd[2] = H_SZ; p.segLd[3] = H_SZ;
        p.nSeg = 4; p.K = KCOMB; p.N = H_SZ + BN;   // 2176 (100 valid in hi tile)
        p.W = W_ch2; p.Wb = W_cm2; p.bias = b_ch2; p.bias_b = b_cm2;
        p.C = new_hidden;
        gemm_tf32<M_FUSED><<<dim3((H_SZ + BN) / BN, B_SZ / BM), block>>>(p);
    }
    // K2: lc_pre = input @ W_ci^T + b_ci + bias  -> g_lc
    {
        GP p = {};
        p.seg[0] = input; p.segEnd[0] = I_SZ; p.segLd[0] = I_SZ; p.nSeg = 1;
        p.K = I_SZ; p.N = H_SZ;
        p.W = W_ci; p.bias = b_ci; p.bias2 = biasv;
        gemm_tf32<M_LCPRE><<<dim3(H_SZ / BN, B_SZ / BM), block>>>(p);
    }
    // K3: out = relu_mid @ W_mo^T + b_mo
    {
        GP p = {};
        p.segEnd[0] = M_SZ; p.segLd[0] = M_SZ; p.nSeg = 1;
        p.K = M_SZ; p.N = O_SZ;
        p.W = W_mo; p.bias = b_mo; p.C = out;
        gemm_tf32<M_OUT><<<dim3(O_SZ / BN, B_SZ / BM), block>>>(p);
    }
    // K4: h_proj = new_hidden @ W_ch^T + b_ch ; writes new_prev_hidden, lc += h_proj
    {
        GP p = {};
        p.seg[0] = new_hidden; p.segEnd[0] = H_SZ; p.segLd[0] = H_SZ; p.nSeg = 1;
        p.K = H_SZ; p.N = H_SZ;
        p.W = W_ch; p.bias = b_ch; p.C = new_prevh;
        gemm_tf32<M_HPROJ><<<dim3(H_SZ / BN, B_SZ / BM), block>>>(p);
    }
    // K5: new_cell = tanh(lc @ W_fc^T + b_fc)
    {
        GP p = {};
        p.segEnd[0] = H_SZ; p.segLd[0] = H_SZ; p.nSeg = 1;
        p.K = H_SZ; p.N = H_SZ;
        p.W = W_fc; p.bias = b_fc; p.C = new_cell;
        gemm_tf32<M_CELL><<<dim3(H_SZ / BN, B_SZ / BM), block>>>(p);
    }
}

// round 5
// speedup vs baseline: 1.2606x; 1.2606x over previous
#include <cuda_runtime.h>
#include <math.h>
#include <stdint.h>

#define B_SZ 4096
#define MFT  256            // B_SZ/16 A-frag blocks per k8 slice
#define I_SZ 1024
#define H_SZ 2048
#define O_SZ 256
#define KCOMB 7168

#define BM 128
#define BN 256
#define BK 32
#define NSTAGES 4
#define THREADS 256
#define STAGE_A_BYTES (BM*BK*4)          // 16384
#define STAGE_BYTES   ((BM+BN)*BK*4)     // 49152
#define SMEM_TOTAL    (NSTAGES*STAGE_BYTES)  // 196608

enum { M_FUSED=0, M_LCPRE=1, M_OUT=2, M_HPROJ=3, M_CELL=4 };

// ---- static scratch (allocation-free per harness rules) ----
__device__ __align__(128) float g_comb_f[(size_t)B_SZ*KCOMB];   // A-frag: [input|hidden|prevh|cell]
__device__ __align__(128) float g_Wch2_f[(size_t)H_SZ*KCOMB];
__device__ __align__(128) float g_Wcm2_f[(size_t)128*KCOMB];    // rows padded 100->128
__device__ __align__(128) float g_Wci_f [(size_t)H_SZ*I_SZ];
__device__ __align__(128) float g_Wch_f [(size_t)H_SZ*H_SZ];
__device__ __align__(128) float g_Wfc_f [(size_t)H_SZ*H_SZ];
__device__ __align__(128) float g_Wmo_f [(size_t)O_SZ*128];     // K padded 100->128
__device__ __align__(128) float g_nh_f  [(size_t)B_SZ*H_SZ];    // A-frag of new_hidden
__device__ __align__(128) float g_lc_f  [(size_t)B_SZ*H_SZ];    // A-frag of lc
__device__ __align__(128) float g_mid_f [(size_t)B_SZ*128];     // A-frag of relu-mid
__device__ __align__(128) float g_mid   [(size_t)B_SZ*128];     // fp32 relu-mid (padded)
__device__ __align__(128) float g_lc    [(size_t)B_SZ*H_SZ];    // fp32 lc accumulator

__device__ __forceinline__ uint32_t f2tf(float x) {
    uint32_t r; asm("cvt.rna.tf32.f32 %0, %1;" : "=r"(r) : "f"(x)); return r;
}

// A-fragment layout (operand [4096, K]):  addr in 32-bit words
// block = (k/8)*MFT + m/16 ; lane = (m&7)*4 + (k&3) ; slot = ((m>>3)&1) | (((k>>2)&1)<<1)
__device__ __forceinline__ size_t a_fidx(int m, int k) {
    size_t blk = (size_t)(k >> 3) * MFT + (m >> 4);
    int lane = ((m & 7) << 2) | (k & 3);
    int slot = ((m >> 3) & 1) | (((k >> 2) & 1) << 1);
    return blk * 128 + lane * 4 + slot;
}
// B-fragment layout (operand [N, K]): 2 k8-slices packed per 16B
// block = (k/16)*(N/8) + n/8 ; lane = (n&7)*4 + (k&3) ; slot = (k>>2)&3
__device__ __forceinline__ size_t b_fidx(int n, int k, int NfT) {
    size_t blk = (size_t)(k >> 4) * NfT + (n >> 3);
    int lane = ((n & 7) << 2) | (k & 3);
    int slot = (k >> 2) & 3;
    return blk * 128 + lane * 4 + slot;
}

__device__ __forceinline__ void cp16(uint32_t s, const void* g) {
    asm volatile("cp.async.cg.shared.global [%0], [%1], 16;\n" :: "r"(s), "l"(g));
}

__device__ __forceinline__ void mma8(float* c, const uint4& a, uint32_t b0, uint32_t b1) {
    asm volatile(
        "mma.sync.aligned.m16n8k8.row.col.f32.tf32.tf32.f32 "
        "{%0,%1,%2,%3}, {%4,%5,%6,%7}, {%8,%9}, {%0,%1,%2,%3};\n"
        : "+f"(c[0]), "+f"(c[1]), "+f"(c[2]), "+f"(c[3])
        : "r"(a.x), "r"(a.y), "r"(a.z), "r"(a.w), "r"(b0), "r"(b1));
}

// ---------------- prep kernels ----------------
__device__ __forceinline__ void bfrag_fill(float* dst, const float* src,
                                           int Nsrc, int Ksrc, int Kpad, int NfT) {
    int n = blockIdx.y;
    int k = blockIdx.x * blockDim.x + threadIdx.x;
    if (k >= Kpad) return;
    float v = (n < Nsrc && k < Ksrc) ? src[(size_t)n * Ksrc + k] : 0.f;
    ((uint32_t*)dst)[b_fidx(n, k, NfT)] = f2tf(v);
}
__global__ void prep_wch2(const float* s){ bfrag_fill(g_Wch2_f, s, H_SZ, KCOMB, KCOMB, H_SZ/8); }
__global__ void prep_wcm2(const float* s){ bfrag_fill(g_Wcm2_f, s, 100,  KCOMB, KCOMB, 16); }
__global__ void prep_wci (const float* s){ bfrag_fill(g_Wci_f,  s, H_SZ, I_SZ,  I_SZ,  H_SZ/8); }
__global__ void prep_wch (const float* s){ bfrag_fill(g_Wch_f,  s, H_SZ, H_SZ,  H_SZ,  H_SZ/8); }
__global__ void prep_wfc (const float* s){ bfrag_fill(g_Wfc_f,  s, H_SZ, H_SZ,  H_SZ,  H_SZ/8); }
__global__ void prep_wmo (const float* s){ bfrag_fill(g_Wmo_f,  s, O_SZ, 100,   128,   O_SZ/8); }

__global__ void prep_comb(const float* in, const float* hid,
                          const float* ph, const float* ce) {
    int m = blockIdx.y;
    int k = blockIdx.x * blockDim.x + threadIdx.x;   // < 7168
    float v;
    if (k < I_SZ)            v = in [(size_t)m*I_SZ + k];
    else if (k < I_SZ+H_SZ)  v = hid[(size_t)m*H_SZ + (k - I_SZ)];
    else if (k < I_SZ+2*H_SZ)v = ph [(size_t)m*H_SZ + (k - I_SZ - H_SZ)];
    else                     v = ce [(size_t)m*H_SZ + (k - I_SZ - 2*H_SZ)];
    ((uint32_t*)g_comb_f)[a_fidx(m, k)] = f2tf(v);
}

__device__ __forceinline__ void afrag_fill(float* dst, const float* src, int Kd) {
    int m = blockIdx.y;
    int k = blockIdx.x * blockDim.x + threadIdx.x;
    if (k >= Kd) return;
    ((uint32_t*)dst)[a_fidx(m, k)] = f2tf(src[(size_t)m * Kd + k]);
}
__global__ void conv_nh (const float* s){ afrag_fill(g_nh_f,  s,     H_SZ); }
__global__ void conv_lc (){               afrag_fill(g_lc_f,  g_lc,  H_SZ); }
__global__ void conv_mid(){               afrag_fill(g_mid_f, g_mid, 128); }

// ---------------- GEMM ----------------
template<int MODE>
__device__ __forceinline__ void epi(int r, int c, float2 v,
                                    const float* bias, const float* bias_b,
                                    const float* bias2, float* C) {
    if (MODE == M_FUSED) {
        if (c < H_SZ) {
            float2 b = *(const float2*)(bias + c);
            *(float2*)(C + (size_t)r*H_SZ + c) = make_float2(v.x+b.x, v.y+b.y);
        } else {
            int c2 = c - H_SZ;
            float2 o = make_float2(0.f, 0.f);
            if (c2 < 100) {
                float2 b = *(const float2*)(bias_b + c2);
                o.x = fmaxf(v.x + b.x, 0.f);
                o.y = fmaxf(v.y + b.y, 0.f);
            }
            *(float2*)(g_mid + (size_t)r*128 + c2) = o;
        }
    } else if (MODE == M_LCPRE) {
        float2 b  = *(const float2*)(bias + c);
        float2 b2 = *(const float2*)(bias2 + c);
        *(float2*)(g_lc + (size_t)r*H_SZ + c) = make_float2(v.x+b.x+b2.x, v.y+b.y+b2.y);
    } else if (MODE == M_OUT) {
        float2 b = *(const float2*)(bias + c);
        *(float2*)(C + (size_t)r*O_SZ + c) = make_float2(v.x+b.x, v.y+b.y);
    } else if (MODE == M_HPROJ) {
        float2 b = *(const float2*)(bias + c);
        float2 hp = make_float2(v.x+b.x, v.y+b.y);
        *(float2*)(C + (size_t)r*H_SZ + c) = hp;          // new_prev_hidden
        float2* lp = (float2*)(g_lc + (size_t)r*H_SZ + c);
        float2 lv = *lp;
        *lp = make_float2(lv.x + hp.x, lv.y + hp.y);
    } else { // M_CELL
        float2 b = *(const float2*)(bias + c);
        *(float2*)(C + (size_t)r*H_SZ + c) = make_float2(tanhf(v.x+b.x), tanhf(v.y+b.y));
    }
}

template<int MODE, int KDIM, int NFT1, int NFT2>
__global__ void __launch_bounds__(THREADS, 1)
tc_gemm(const float* __restrict__ bias, const float* __restrict__ bias_b,
        const float* __restrict__ bias2, float* __restrict__ C)
{
    extern __shared__ __align__(1024) char smem[];
    const uint32_t sbase = (uint32_t)__cvta_generic_to_shared(smem);
    const int tid  = threadIdx.x;
    const int lane = tid & 31;
    const int wid  = tid >> 5;
    const int wm   = wid >> 2;          // 0..1  (M)
    const int wn   = wid & 3;           // 0..3  (N)
    const int mBase = blockIdx.y * BM;
    const int nBase = blockIdx.x * BN;

    const float* Af =
        (MODE==M_FUSED || MODE==M_LCPRE) ? g_comb_f :
        (MODE==M_OUT)   ? g_mid_f :
        (MODE==M_HPROJ) ? g_nh_f : g_lc_f;
    const float* Bf =
        (MODE==M_FUSED) ? g_Wch2_f :
        (MODE==M_LCPRE) ? g_Wci_f :
        (MODE==M_OUT)   ? g_Wmo_f :
        (MODE==M_HPROJ) ? g_Wch_f : g_Wfc_f;

    int NfT = NFT1, nMMA = BN, nBlk = nBase >> 3;
    if (MODE == M_FUSED && nBase >= H_SZ) {   // relu-mid tile
        Bf = g_Wcm2_f; NfT = NFT2; nMMA = 128; nBlk = 0;
    }
    const int NfTile = nMMA >> 3;             // 32 or 16
    const bool act = (wn * 64) < nMMA;
    const int nK = KDIM / BK;                 // >= 4 always

    auto load_stage = [&](int kt) {
        const int s = kt & (NSTAGES - 1);
        const uint32_t stA = sbase + s * STAGE_BYTES;
        const uint32_t stB = stA + STAGE_A_BYTES;
        const int k0 = kt * BK;
        #pragma unroll
        for (int i = 0; i < 4; i++) {                 // A: 1024 x 16B units
            int u = tid + i * THREADS;
            int ks = u >> 8;
            int rem = u & 255;
            const float* src = Af + ((size_t)((k0>>3)+ks)*MFT + (mBase>>4))*128 + rem*4;
            cp16(stA + u*16, src);
        }
        const int bunits = nMMA * 8;                  // 2048 or 1024 units
        const int upk = nMMA * 4;
        for (int u = tid; u < bunits; u += THREADS) {
            int kt16 = (u >= upk) ? 1 : 0;
            int rem = u - kt16 * upk;
            const float* src = Bf + ((size_t)((k0>>4)+kt16)*NfT + nBlk)*128 + rem*4;
            cp16(stB + u*16, src);
        }
    };

    float acc[4][8][4];
    #pragma unroll
    for (int a = 0; a < 4; a++)
        #pragma unroll
        for (int b = 0; b < 8; b++)
            #pragma unroll
            for (int c = 0; c < 4; c++) acc[a][b][c] = 0.f;

    #pragma unroll
    for (int st = 0; st < NSTAGES - 1; st++) {
        load_stage(st);
        asm volatile("cp.async.commit_group;\n");
    }

    for (int kt = 0; kt < nK; kt++) {
        asm volatile("cp.async.wait_group %0;\n" :: "n"(NSTAGES - 2));
        __syncthreads();
        if (kt + NSTAGES - 1 < nK) load_stage(kt + NSTAGES - 1);
        asm volatile("cp.async.commit_group;\n");

        const int s = kt & (NSTAGES - 1);
        const uint32_t stA = sbase + s * STAGE_BYTES;
        const uint32_t stB = stA + STAGE_A_BYTES;

        if (act) {
            uint4 breg[8];
            #pragma unroll
            for (int kk = 0; kk < 4; kk++) {
                uint4 areg[4];
                #pragma unroll
                for (int i = 0; i < 4; i++) {
                    uint32_t addr = stA + (((kk*8) + wm*4 + i)*32 + lane)*16;
                    asm volatile("ld.shared.v4.b32 {%0,%1,%2,%3}, [%4];"
                        : "=r"(areg[i].x), "=r"(areg[i].y),
                          "=r"(areg[i].z), "=r"(areg[i].w) : "r"(addr));
                }
                if ((kk & 1) == 0) {
                    const int kt16 = kk >> 1;
                    #pragma unroll
                    for (int j = 0; j < 8; j++) {
                        uint32_t addr = stB + ((kt16*NfTile + wn*8 + j)*32 + lane)*16;
                        asm volatile("ld.shared.v4.b32 {%0,%1,%2,%3}, [%4];"
                            : "=r"(breg[j].x), "=r"(breg[j].y),
                              "=r"(breg[j].z), "=r"(breg[j].w) : "r"(addr));
                    }
                }
                #pragma unroll
                for (int mi = 0; mi < 4; mi++)
                    #pragma unroll
                    for (int j = 0; j < 8; j++) {
                        uint32_t b0 = (kk & 1) ? breg[j].z : breg[j].x;
                        uint32_t b1 = (kk & 1) ? breg[j].w : breg[j].y;
                        mma8(acc[mi][j], areg[mi], b0, b1);
                    }
            }
        }
    }

    if (act) {
        const int g = lane >> 2, l = lane & 3;
        #pragma unroll
        for (int mi = 0; mi < 4; mi++) {
            int r0 = mBase + wm*64 + mi*16 + g;
            #pragma unroll
            for (int j = 0; j < 8; j++) {
                int col = nBase + wn*64 + j*8 + l*2;
                epi<MODE>(r0,     col, make_float2(acc[mi][j][0], acc[mi][j][1]),
                          bias, bias_b, bias2, C);
                epi<MODE>(r0 + 8, col, make_float2(acc[mi][j][2], acc[mi][j][3]),
                          bias, bias_b, bias2, C);
            }
        }
    }
}

extern "C" void kernel_launch(void* const* d_in, const int* in_sizes, int n_in,
                              void* d_out, int out_size)
{
    const float* input = (const float*)d_in[0];
    const float* hidden = (const float*)d_in[1];
    const float* prevh  = (const float*)d_in[2];
    const float* cell   = (const float*)d_in[3];
    const float* W_ch2 = (const float*)d_in[4];
    const float* b_ch2 = (const float*)d_in[5];
    const float* W_cm2 = (const float*)d_in[6];
    const float* b_cm2 = (const float*)d_in[7];
    const float* W_mo  = (const float*)d_in[8];
    const float* b_mo  = (const float*)d_in[9];
    const float* W_ci  = (const float*)d_in[10];
    const float* b_ci  = (const float*)d_in[11];
    const float* W_ch  = (const float*)d_in[12];
    const float* b_ch  = (const float*)d_in[13];
    const float* W_fc  = (const float*)d_in[14];
    const float* b_fc  = (const float*)d_in[15];
    const float* biasv = (const float*)d_in[16];

    float* out        = (float*)d_out;                       // [B, 256]
    float* new_hidden = out + (size_t)B_SZ * O_SZ;           // [B, 2048]
    float* new_cell   = new_hidden + (size_t)B_SZ * H_SZ;    // [B, 2048]
    float* new_prevh  = new_cell + (size_t)B_SZ * H_SZ;      // [B, 2048]

    static bool attr_done = false;
    if (!attr_done) {
        cudaFuncSetAttribute((const void*)tc_gemm<M_FUSED, KCOMB, 256, 16>,
                             cudaFuncAttributeMaxDynamicSharedMemorySize, SMEM_TOTAL);
        cudaFuncSetAttribute((const void*)tc_gemm<M_LCPRE, I_SZ, 256, 0>,
                             cudaFuncAttributeMaxDynamicSharedMemorySize, SMEM_TOTAL);
        cudaFuncSetAttribute((const void*)tc_gemm<M_OUT, 128, 32, 0>,
                             cudaFuncAttributeMaxDynamicSharedMemorySize, SMEM_TOTAL);
        cudaFuncSetAttribute((const void*)tc_gemm<M_HPROJ, H_SZ, 256, 0>,
                             cudaFuncAttributeMaxDynamicSharedMemorySize, SMEM_TOTAL);
        cudaFuncSetAttribute((const void*)tc_gemm<M_CELL, H_SZ, 256, 0>,
                             cudaFuncAttributeMaxDynamicSharedMemorySize, SMEM_TOTAL);
        attr_done = true;
    }

    // ---- prep: fragment-format weights + combined activations ----
    prep_comb<<<dim3(KCOMB/256, B_SZ), 256>>>(input, hidden, prevh, cell);
    prep_wch2<<<dim3(KCOMB/256, H_SZ), 256>>>(W_ch2);
    prep_wcm2<<<dim3(KCOMB/256, 128), 256>>>(W_cm2);
    prep_wci <<<dim3(I_SZ/256, H_SZ), 256>>>(W_ci);
    prep_wch <<<dim3(H_SZ/256, H_SZ), 256>>>(W_ch);
    prep_wfc <<<dim3(H_SZ/256, H_SZ), 256>>>(W_fc);
    prep_wmo <<<dim3(1, O_SZ), 128>>>(W_mo);

    // ---- K1: fused new_hidden + relu-mid (K = 7168) ----
    tc_gemm<M_FUSED, KCOMB, 256, 16>
        <<<dim3(H_SZ/BN + 1, B_SZ/BM), THREADS, SMEM_TOTAL>>>(b_ch2, b_cm2, nullptr, new_hidden);
    conv_nh <<<dim3(H_SZ/256, B_SZ), 256>>>(new_hidden);
    conv_mid<<<dim3(1, B_SZ), 128>>>();

    // ---- K2: lc_pre = input @ W_ci^T + b_ci + bias -> g_lc ----
    tc_gemm<M_LCPRE, I_SZ, 256, 0>
        <<<dim3(H_SZ/BN, B_SZ/BM), THREADS, SMEM_TOTAL>>>(b_ci, nullptr, biasv, nullptr);

    // ---- K3: out = mid @ W_mo^T + b_mo ----
    tc_gemm<M_OUT, 128, 32, 0>
        <<<dim3(1, B_SZ/BM), THREADS, SMEM_TOTAL>>>(b_mo, nullptr, nullptr, out);

    // ---- K4: h_proj = new_hidden @ W_ch^T + b_ch -> new_prevh; g_lc += ----
    tc_gemm<M_HPROJ, H_SZ, 256, 0>
        <<<dim3(H_SZ/BN, B_SZ/BM), THREADS, SMEM_TOTAL>>>(b_ch, nullptr, nullptr, new_prevh);
    conv_lc<<<dim3(H_SZ/256, B_SZ), 256>>>();

    // ---- K5: new_cell = tanh(lc @ W_fc^T + b_fc) ----
    tc_gemm<M_CELL, H_SZ, 256, 0>
        <<<dim3(H_SZ/BN, B_SZ/BM), THREADS, SMEM_TOTAL>>>(b_fc, nullptr, nullptr, new_cell);
}